// round 6
// baseline (speedup 1.0000x reference)
#include <cuda_runtime.h>
#include <cuda_bf16.h>
#include <math.h>
#include <stdint.h>

// Problem constants
#define BB   32
#define INF  128
#define HH   1024
#define OUTF 128
#define KCAT (INF + HH)   // 1152
#define TPB  256
#define STAGES 3

// Scratch (allocation-free rule: __device__ globals)
__device__ float g_c0[BB * HH];
__device__ float g_c1[BB * HH];
__device__ float g_c2[BB * HH];
__device__ float g_logits[BB * OUTF];

// ---------------- PTX helpers ----------------
__device__ __forceinline__ uint32_t smem_u32(const void* p) {
    uint32_t a;
    asm("{ .reg .u64 t; cvta.to.shared.u64 t, %1; cvt.u32.u64 %0, t; }" : "=r"(a) : "l"(p));
    return a;
}
__device__ __forceinline__ void mbar_init(uint32_t mbar, uint32_t count) {
    asm volatile("mbarrier.init.shared.b64 [%0], %1;" :: "r"(mbar), "r"(count) : "memory");
}
__device__ __forceinline__ void mbar_expect_tx(uint32_t mbar, uint32_t bytes) {
    asm volatile("mbarrier.arrive.expect_tx.shared.b64 _, [%0], %1;" :: "r"(mbar), "r"(bytes) : "memory");
}
__device__ __forceinline__ void mbar_wait(uint32_t mbar, uint32_t phase) {
    asm volatile(
        "{\n\t.reg .pred P;\n\t"
        "WL_%=:\n\t"
        "mbarrier.try_wait.parity.acquire.cta.shared::cta.b64 P, [%0], %1, 0x989680;\n\t"
        "@P bra WD_%=;\n\t"
        "bra WL_%=;\n\t"
        "WD_%=:\n\t}"
        :: "r"(mbar), "r"(phase) : "memory");
}
__device__ __forceinline__ void tma_bulk_g2s(uint32_t dst_smem, const void* src, uint32_t bytes, uint32_t mbar) {
    asm volatile(
        "cp.async.bulk.shared::cta.global.mbarrier::complete_tx::bytes [%0], [%1], %2, [%3];"
        :: "r"(dst_smem), "l"(src), "r"(bytes), "r"(mbar) : "memory");
}
__device__ __forceinline__ void fence_proxy_async_cta() {
    asm volatile("fence.proxy.async.shared::cta;" ::: "memory");
}

// ---------------------------------------------------------------------------
// TMA-streamed matvec layer. Chunk = 8 rows (one per warp), STAGES-deep ring.
// Activation vector lives in registers (reloaded on batch change).
// ---------------------------------------------------------------------------
template <int K, bool TANH, bool CONCAT>
__global__ __launch_bounds__(TPB, 1) void tma_layer_kernel(
    const float* __restrict__ W, const float* __restrict__ bias,
    const float* __restrict__ inA, const float* __restrict__ inB,
    float* __restrict__ outp, int Hout, int nchunks, int per)
{
    constexpr int CHUNK_BYTES  = 8 * K * 4;
    constexpr int CHUNK_FLOATS = 8 * K;
    constexpr int NJ = K / 128;            // float4s per lane for one row

    extern __shared__ __align__(128) unsigned char smem_raw[];
    float*    buf  = reinterpret_cast<float*>(smem_raw);
    uint64_t* mbar = reinterpret_cast<uint64_t*>(smem_raw + STAGES * CHUNK_BYTES);

    const int tid  = threadIdx.x;
    const int warp = tid >> 5;
    const int lane = tid & 31;

    const uint32_t mb0 = smem_u32(mbar);

    if (tid == 0) {
#pragma unroll
        for (int s = 0; s < STAGES; s++) mbar_init(mb0 + s * 8, 1);
        fence_proxy_async_cta();
    }
    __syncthreads();

    const int c0 = blockIdx.x * per;
    const int c1 = min(c0 + per, nchunks);
    if (c0 >= c1) return;

    // Prologue: fill the ring
    if (tid == 0) {
#pragma unroll
        for (int i = 0; i < STAGES; i++) {
            int c = c0 + i;
            if (c < c1) {
                uint32_t dst = smem_u32(buf + i * CHUNK_FLOATS);
                mbar_expect_tx(mb0 + i * 8, CHUNK_BYTES);
                tma_bulk_g2s(dst, (const char*)W + (size_t)c * CHUNK_BYTES, CHUNK_BYTES, mb0 + i * 8);
            }
        }
    }

    float4 xr[NJ];
    int cur_b = -1;

    for (int c = c0; c < c1; ++c) {
        const int idx  = c - c0;
        const int slot = idx % STAGES;
        const uint32_t ph = (uint32_t)((idx / STAGES) & 1);
        const int rowbase = c * 8;
        const int b = rowbase / Hout;

        if (b != cur_b) {      // reload activation registers (L2-hot)
            if (CONCAT) {
                const float4* xa = reinterpret_cast<const float4*>(inA + (size_t)b * INF);
                const float4* xb = reinterpret_cast<const float4*>(inB + (size_t)b * HH);
#pragma unroll
                for (int j = 0; j < NJ; j++) {
                    int c4 = j * 32 + lane;
                    xr[j] = (c4 < INF / 4) ? xa[c4] : xb[c4 - INF / 4];
                }
            } else {
                const float4* xa = reinterpret_cast<const float4*>(inA + (size_t)b * K);
#pragma unroll
                for (int j = 0; j < NJ; j++)
                    xr[j] = xa[j * 32 + lane];
            }
            cur_b = b;
        }

        mbar_wait(mb0 + slot * 8, ph);

        const float4* __restrict__ wrow =
            reinterpret_cast<const float4*>(buf + slot * CHUNK_FLOATS + warp * K);
        float s = 0.f;
#pragma unroll
        for (int j = 0; j < NJ; j++) {
            float4 a = wrow[j * 32 + lane];
            s += a.x * xr[j].x + a.y * xr[j].y + a.z * xr[j].z + a.w * xr[j].w;
        }
#pragma unroll
        for (int off = 16; off; off >>= 1)
            s += __shfl_xor_sync(0xFFFFFFFFu, s, off);

        if (lane == 0) {
            const int row = rowbase + warp;
            const int o   = row - b * Hout;
            float v = s + bias[o];
            outp[row] = TANH ? tanhf(v) : v;
        }

        __syncthreads();   // all warps done with this slot
        if (tid == 0 && c + STAGES < c1) {
            uint32_t dst = smem_u32(buf + slot * CHUNK_FLOATS);
            mbar_expect_tx(mb0 + slot * 8, CHUNK_BYTES);
            tma_bulk_g2s(dst, (const char*)W + (size_t)(c + STAGES) * CHUNK_BYTES,
                         CHUNK_BYTES, mb0 + slot * 8);
        }
    }
}

// log_softmax over 128 logits per batch; one warp per batch row.
__global__ void log_softmax_kernel(float* __restrict__ out) {
    const int warp = threadIdx.x >> 5;   // 0..31 (single block of 1024)
    const int lane = threadIdx.x & 31;
    const float* l = g_logits + warp * OUTF;

    float v[4];
#pragma unroll
    for (int i = 0; i < 4; i++) v[i] = l[i * 32 + lane];

    float m = fmaxf(fmaxf(v[0], v[1]), fmaxf(v[2], v[3]));
#pragma unroll
    for (int off = 16; off; off >>= 1)
        m = fmaxf(m, __shfl_xor_sync(0xFFFFFFFFu, m, off));

    float s = 0.f;
#pragma unroll
    for (int i = 0; i < 4; i++) s += __expf(v[i] - m);
#pragma unroll
    for (int off = 16; off; off >>= 1)
        s += __shfl_xor_sync(0xFFFFFFFFu, s, off);

    float lse = m + logf(s);
#pragma unroll
    for (int i = 0; i < 4; i++)
        out[warp * OUTF + i * 32 + lane] = v[i] - lse;
}

extern "C" void kernel_launch(void* const* d_in, const int* in_sizes, int n_in,
                              void* d_out, int out_size) {
    const float* x      = (const float*)d_in[0];
    const float* hidden = (const float*)d_in[1];
    const float* W0 = (const float*)d_in[2];
    const float* b0 = (const float*)d_in[3];
    const float* W1 = (const float*)d_in[4];
    const float* b1 = (const float*)d_in[5];
    const float* W2 = (const float*)d_in[6];
    const float* b2 = (const float*)d_in[7];
    const float* Wh = (const float*)d_in[8];
    const float* bh = (const float*)d_in[9];
    const float* Wo = (const float*)d_in[10];
    const float* bo = (const float*)d_in[11];

    float* out = (float*)d_out;                 // [B*OUT] log_softmax, then [B*H] new_hidden
    float* new_hidden = out + BB * OUTF;

    float *c0p, *c1p, *c2p;
    cudaGetSymbolAddress((void**)&c0p, g_c0);
    cudaGetSymbolAddress((void**)&c1p, g_c1);
    cudaGetSymbolAddress((void**)&c2p, g_c2);
    float* logits;
    cudaGetSymbolAddress((void**)&logits, g_logits);

    const int SMEM0 = STAGES * 8 * KCAT * 4 + 64;   // 110656
    const int SMEM1 = STAGES * 8 * HH * 4 + 64;     // 98368

    static bool attr_done = false;
    if (!attr_done) {
        cudaFuncSetAttribute(tma_layer_kernel<KCAT, true,  true >,
                             cudaFuncAttributeMaxDynamicSharedMemorySize, SMEM0);
        cudaFuncSetAttribute(tma_layer_kernel<HH,   true,  false>,
                             cudaFuncAttributeMaxDynamicSharedMemorySize, SMEM1);
        cudaFuncSetAttribute(tma_layer_kernel<HH,   false, false>,
                             cudaFuncAttributeMaxDynamicSharedMemorySize, SMEM1);
        attr_done = true;
    }

    int dev = 0, sms = 0;
    cudaGetDevice(&dev);
    cudaDeviceGetAttribute(&sms, cudaDevAttrMultiProcessorCount, dev);
    if (sms < 1) sms = 148;

    const int NCH_H  = (BB * HH) / 8;     // 4096 chunks per H-output layer
    const int NCH_O  = (BB * OUTF) / 8;   // 512

    int nbH = sms; if (nbH > NCH_H) nbH = NCH_H;
    int perH = (NCH_H + nbH - 1) / nbH;
    int nbO = sms; if (nbO > NCH_O) nbO = NCH_O;
    int perO = (NCH_O + nbO - 1) / nbO;

    tma_layer_kernel<KCAT, true,  true ><<<nbH, TPB, SMEM0>>>(W0, b0, x,   hidden,  c0p,        HH,   NCH_H, perH);
    tma_layer_kernel<HH,   true,  false><<<nbH, TPB, SMEM1>>>(W1, b1, c0p, nullptr, c1p,        HH,   NCH_H, perH);
    tma_layer_kernel<HH,   true,  false><<<nbH, TPB, SMEM1>>>(W2, b2, c1p, nullptr, c2p,        HH,   NCH_H, perH);
    tma_layer_kernel<HH,   true,  false><<<nbH, TPB, SMEM1>>>(Wh, bh, c2p, nullptr, new_hidden, HH,   NCH_H, perH);
    tma_layer_kernel<HH,   false, false><<<nbO, TPB, SMEM1>>>(Wo, bo, c2p, nullptr, logits,     OUTF, NCH_O, perO);
    log_softmax_kernel<<<1, BB * 32>>>(out);

    (void)in_sizes; (void)n_in; (void)out_size;
}

// round 7
// speedup vs baseline: 1.3909x; 1.3909x over previous
#include <cuda_runtime.h>
#include <cuda_bf16.h>
#include <math.h>

// Problem constants
#define BB   32
#define INF  128
#define HH   1024
#define OUTF 128
#define KCAT (INF + HH)   // 1152
#define TPB  256
#define RPB  8            // rows (warps) per block
#define HB   16           // batches per chain (BB/2)

// Scratch (allocation-free rule: __device__ globals)
__device__ float g_c0[BB * HH];
__device__ float g_c1[BB * HH];
__device__ float g_c2[BB * HH];
__device__ float g_logits[BB * OUTF];

// ---------------------------------------------------------------------------
// R2-proven matvec tile kernel: 8 warps/block = 8 consecutive rows of ONE
// batch; activation staged in smem once; W front-batched with __ldcs.
// row_off shifts the tile range (per-chain half).
// ---------------------------------------------------------------------------
template <int K, bool LAYER0>
__global__ __launch_bounds__(TPB) void matvec_kernel(
    const float* __restrict__ W, const float* __restrict__ bias,
    const float* __restrict__ in0,   // LAYER0: x ; else: activations [B,K]
    const float* __restrict__ in1,   // LAYER0: hidden ; else unused
    float* __restrict__ out, int Hout, int row_off)
{
    __shared__ float4 xs[K / 4];

    const int rowbase = row_off + blockIdx.x * RPB;
    const int b = rowbase / Hout;

    if (LAYER0) {
        const float4* xv = reinterpret_cast<const float4*>(in0 + (size_t)b * INF);
        const float4* hv = reinterpret_cast<const float4*>(in1 + (size_t)b * HH);
#pragma unroll
        for (int i = threadIdx.x; i < K / 4; i += TPB)
            xs[i] = (i < INF / 4) ? xv[i] : hv[i - INF / 4];
    } else {
        const float4* src = reinterpret_cast<const float4*>(in0 + (size_t)b * K);
#pragma unroll
        for (int i = threadIdx.x; i < K / 4; i += TPB)
            xs[i] = src[i];
    }
    __syncthreads();

    const int warp = threadIdx.x >> 5;
    const int lane = threadIdx.x & 31;
    const int row  = rowbase + warp;
    const int o    = row - b * Hout;

    const float4* __restrict__ Wr = reinterpret_cast<const float4*>(W + (size_t)row * K);
    constexpr int NIT = K / 128;

    float4 w[NIT];
#pragma unroll
    for (int j = 0; j < NIT; j++)
        w[j] = __ldcs(Wr + j * 32 + lane);

    float sum = 0.f;
#pragma unroll
    for (int j = 0; j < NIT; j++) {
        float4 v = xs[j * 32 + lane];
        sum += w[j].x * v.x + w[j].y * v.y + w[j].z * v.z + w[j].w * v.w;
    }
#pragma unroll
    for (int off = 16; off; off >>= 1)
        sum += __shfl_xor_sync(0xFFFFFFFFu, sum, off);

    if (lane == 0)
        out[row] = tanhf(sum + bias[o]);
}

// Fused heads (half-batch): blocks [0,NBH) -> Wh rows of batches [boff,boff+HB),
// blocks [NBH,NBH+NBO) -> Wo rows of the same batches.
__global__ __launch_bounds__(TPB) void heads_kernel(
    const float* __restrict__ Wh, const float* __restrict__ bh,
    const float* __restrict__ Wo, const float* __restrict__ bo,
    float* __restrict__ new_hidden_out, int boff)
{
    __shared__ float4 xs[HH / 4];

    const int NBH = (HB * HH) / RPB;   // 2048 blocks for Wh half
    const bool is_h = (blockIdx.x < NBH);
    int rowbase, b, Hout;
    const float* Wbase; const float* bias;
    if (is_h) { rowbase = boff * HH  + blockIdx.x * RPB;          Hout = HH;   Wbase = Wh; bias = bh; }
    else      { rowbase = boff * OUTF + (blockIdx.x - NBH) * RPB; Hout = OUTF; Wbase = Wo; bias = bo; }
    b = rowbase / Hout;

    {
        const float4* src = reinterpret_cast<const float4*>(g_c2 + (size_t)b * HH);
#pragma unroll
        for (int i = threadIdx.x; i < HH / 4; i += TPB)
            xs[i] = src[i];
    }
    __syncthreads();

    const int warp = threadIdx.x >> 5;
    const int lane = threadIdx.x & 31;
    const int row  = rowbase + warp;
    const int o    = row - b * Hout;

    const float4* __restrict__ Wr = reinterpret_cast<const float4*>(Wbase + (size_t)row * HH);
    constexpr int NIT = HH / 128;

    float4 w[NIT];
#pragma unroll
    for (int j = 0; j < NIT; j++)
        w[j] = __ldcs(Wr + j * 32 + lane);

    float sum = 0.f;
#pragma unroll
    for (int j = 0; j < NIT; j++) {
        float4 v = xs[j * 32 + lane];
        sum += w[j].x * v.x + w[j].y * v.y + w[j].z * v.z + w[j].w * v.w;
    }
#pragma unroll
    for (int off = 16; off; off >>= 1)
        sum += __shfl_xor_sync(0xFFFFFFFFu, sum, off);

    if (lane == 0) {
        if (is_h) new_hidden_out[row] = tanhf(sum + bias[o]);
        else      g_logits[row] = sum + bias[o];
    }
}

// log_softmax for batches [boff, boff+HB); one warp per batch (512 threads).
__global__ void log_softmax_kernel(float* __restrict__ out, int boff) {
    const int warp = threadIdx.x >> 5;   // 0..15
    const int lane = threadIdx.x & 31;
    const int bq = boff + warp;
    const float* l = g_logits + bq * OUTF;

    float v[4];
#pragma unroll
    for (int i = 0; i < 4; i++) v[i] = l[i * 32 + lane];

    float m = fmaxf(fmaxf(v[0], v[1]), fmaxf(v[2], v[3]));
#pragma unroll
    for (int off = 16; off; off >>= 1)
        m = fmaxf(m, __shfl_xor_sync(0xFFFFFFFFu, m, off));

    float s = 0.f;
#pragma unroll
    for (int i = 0; i < 4; i++) s += __expf(v[i] - m);
#pragma unroll
    for (int off = 16; off; off >>= 1)
        s += __shfl_xor_sync(0xFFFFFFFFu, s, off);

    float lse = m + logf(s);
#pragma unroll
    for (int i = 0; i < 4; i++)
        out[bq * OUTF + i * 32 + lane] = v[i] - lse;
}

extern "C" void kernel_launch(void* const* d_in, const int* in_sizes, int n_in,
                              void* d_out, int out_size) {
    const float* x      = (const float*)d_in[0];
    const float* hidden = (const float*)d_in[1];
    const float* W0 = (const float*)d_in[2];
    const float* b0 = (const float*)d_in[3];
    const float* W1 = (const float*)d_in[4];
    const float* b1 = (const float*)d_in[5];
    const float* W2 = (const float*)d_in[6];
    const float* b2 = (const float*)d_in[7];
    const float* Wh = (const float*)d_in[8];
    const float* bh = (const float*)d_in[9];
    const float* Wo = (const float*)d_in[10];
    const float* bo = (const float*)d_in[11];

    float* out = (float*)d_out;                 // [B*OUT] log_softmax, then [B*H] new_hidden
    float* new_hidden = out + BB * OUTF;

    float *c0, *c1, *c2;
    cudaGetSymbolAddress((void**)&c0, g_c0);
    cudaGetSymbolAddress((void**)&c1, g_c1);
    cudaGetSymbolAddress((void**)&c2, g_c2);

    // One side stream + fork/join events (created once; capture-legal pattern).
    static cudaStream_t s1 = nullptr;
    static cudaEvent_t evFork = nullptr, evJoin = nullptr;
    if (!s1) {
        cudaStreamCreateWithFlags(&s1, cudaStreamNonBlocking);
        cudaEventCreateWithFlags(&evFork, cudaEventDisableTiming);
        cudaEventCreateWithFlags(&evJoin, cudaEventDisableTiming);
    }

    const int BLKS_L = (HB * HH) / RPB;                    // 2048 per half-layer
    const int BLKS_HEADS = BLKS_L + (HB * OUTF) / RPB;     // 2304
    const int ROFF = HB * HH;                              // 16384 row offset (H layers)

    // Fork: chain B (batches 16..31) on s1.
    cudaEventRecord(evFork, 0);
    cudaStreamWaitEvent(s1, evFork, 0);

    // Chain A: batches 0..15 on default stream
    matvec_kernel<KCAT, true ><<<BLKS_L, TPB, 0, 0>>>(W0, b0, x,  hidden,  c0, HH, 0);
    matvec_kernel<HH,   false><<<BLKS_L, TPB, 0, 0>>>(W1, b1, c0, nullptr, c1, HH, 0);
    matvec_kernel<HH,   false><<<BLKS_L, TPB, 0, 0>>>(W2, b2, c1, nullptr, c2, HH, 0);
    heads_kernel<<<BLKS_HEADS, TPB, 0, 0>>>(Wh, bh, Wo, bo, new_hidden, 0);
    log_softmax_kernel<<<1, HB * 32, 0, 0>>>(out, 0);

    // Chain B: batches 16..31 on s1
    matvec_kernel<KCAT, true ><<<BLKS_L, TPB, 0, s1>>>(W0, b0, x,  hidden,  c0, HH, ROFF);
    matvec_kernel<HH,   false><<<BLKS_L, TPB, 0, s1>>>(W1, b1, c0, nullptr, c1, HH, ROFF);
    matvec_kernel<HH,   false><<<BLKS_L, TPB, 0, s1>>>(W2, b2, c1, nullptr, c2, HH, ROFF);
    heads_kernel<<<BLKS_HEADS, TPB, 0, s1>>>(Wh, bh, Wo, bo, new_hidden, HB);
    log_softmax_kernel<<<1, HB * 32, 0, s1>>>(out, HB);

    // Join back to the capture stream.
    cudaEventRecord(evJoin, s1);
    cudaStreamWaitEvent(0, evJoin, 0);

    (void)in_sizes; (void)n_in; (void)out_size;
}